// round 13
// baseline (speedup 1.0000x reference)
#include <cuda_runtime.h>
#include <math.h>
#include <cstdint>

#define CC     128    // centers
#define DD     64     // latent dim
#define TILE_M 128    // candidates per tile
#define NWORK  444    // 3 CTAs x 148 SMs
#define EPSF   1e-6f
#define TINV   10.0f  // 1/TEMP
#define DTF    0.1f

__device__ float g_partial[4096];
__device__ float g_inv;

// ---------------- helpers ----------------
__device__ __forceinline__ uint32_t smem_u32(const void* p) {
    uint32_t a;
    asm("{ .reg .u64 t; cvta.to.shared.u64 t, %1; cvt.u32.u64 %0, t; }" : "=r"(a) : "l"(p));
    return a;
}
__device__ __forceinline__ float to_tf32(float x) {
    uint32_t r;
    asm("cvt.rna.tf32.f32 %0, %1;" : "=r"(r) : "f"(x));
    return __uint_as_float(r);
}
__device__ __forceinline__ void ldsm_x4(uint32_t& r0, uint32_t& r1, uint32_t& r2, uint32_t& r3,
                                        uint32_t addr) {
    asm volatile("ldmatrix.sync.aligned.m8n8.x4.shared.b16 {%0,%1,%2,%3}, [%4];"
                 : "=r"(r0), "=r"(r1), "=r"(r2), "=r"(r3) : "r"(addr));
}
__device__ __forceinline__ void mma_tf32(float* c,
                                         uint32_t a0, uint32_t a1, uint32_t a2, uint32_t a3,
                                         uint32_t b0, uint32_t b1) {
    asm volatile("mma.sync.aligned.m16n8k8.row.col.f32.tf32.tf32.f32 "
                 "{%0,%1,%2,%3}, {%4,%5,%6,%7}, {%8,%9}, {%0,%1,%2,%3};"
                 : "+f"(c[0]), "+f"(c[1]), "+f"(c[2]), "+f"(c[3])
                 : "r"(a0), "r"(a1), "r"(a2), "r"(a3), "r"(b0), "r"(b1));
}
__device__ __forceinline__ float rsq(float x) {
    float r;
    asm("rsqrt.approx.f32 %0, %1;" : "=f"(r) : "f"(x));
    return r;
}

// dyn smem: A tile 32KB + B tile 32KB, row-major tf32 with 16B-chunk XOR swizzle
#define DSMEM_BYTES 65536

__global__ __launch_bounds__(256, 3)
void pot_kernel(const float* __restrict__ cand,
                const float* __restrict__ centers,
                const float* __restrict__ mus,
                const float* __restrict__ q,
                float* __restrict__ qout,
                float* __restrict__ att, int N, int ntiles) {
    extern __shared__ float dsm[];
    __shared__ float s_zn[TILE_M], s_cn[CC], s_mu[CC], s_qd[CC], s_pot[TILE_M], s_red[4];
    __shared__ float s_qpot;

    int tid  = threadIdx.x;
    int lane = tid & 31;
    int wid  = tid >> 5;

    float* aS = dsm;          // 8192 floats: 128 rows x 64, chunk(row,c4) at c4^(row&7)
    float* bS = dsm + 8192;   // same for centers

    // -------- query flow field (folded into last worker; dsm as scratch) --------
    if (blockIdx.x == NWORK - 1) {
        float* qs  = dsm;
        float* w   = dsm + 64;
        float* red = dsm + 192;
        if (tid < DD) qs[tid] = q[tid];
        __syncthreads();
        {
            int j = tid >> 1, h = tid & 1;
            const float4* cr = (const float4*)(centers + j * DD + h * 32);
            float d2 = 0.f;
            #pragma unroll
            for (int k2 = 0; k2 < 8; ++k2) {
                float4 v = cr[k2];
                float4 qv = *(const float4*)(qs + h * 32 + k2 * 4);
                float dx = v.x - qv.x, dy = v.y - qv.y, dz = v.z - qv.z, dw = v.w - qv.w;
                d2 = fmaf(dx, dx, fmaf(dy, dy, fmaf(dz, dz, fmaf(dw, dw, d2))));
            }
            d2 += __shfl_xor_sync(0xFFFFFFFFu, d2, 1);
            if (h == 0) {
                d2 = fmaxf(d2, 1e-12f);
                float r = sqrtf(d2);
                w[j] = mus[j] / (r * r * r + EPSF);
            }
        }
        __syncthreads();
        {
            int d = tid & 63, jg = tid >> 6;
            float s = 0.f;
            #pragma unroll 8
            for (int j2 = jg * 32; j2 < jg * 32 + 32; ++j2)
                s = fmaf(w[j2], centers[j2 * DD + d] - qs[d], s);
            red[tid] = s;
            __syncthreads();
            if (tid < DD)
                qout[tid] = fmaf(DTF, red[tid] + red[tid + 64] + red[tid + 128] + red[tid + 192],
                                 qs[tid]);
        }
        __syncthreads();   // scratch reuse barrier before B staging
    }

    // -------- stage B (centers) ONCE per CTA; norms + query dists --------
    #pragma unroll
    for (int it = 0; it < 8; ++it) {
        int idx = tid + 256 * it;              // 0..2047
        int row = idx >> 4, c4 = idx & 15;
        float4 v  = ((const float4*)centers)[row * 16 + c4];
        float4 qv = ((const float4*)q)[c4];

        float pc = fmaf(v.x, v.x, fmaf(v.y, v.y, fmaf(v.z, v.z, v.w * v.w)));
        float dx = v.x - qv.x, dy = v.y - qv.y, dz = v.z - qv.z, dw = v.w - qv.w;
        float pd = fmaf(dx, dx, fmaf(dy, dy, fmaf(dz, dz, dw * dw)));
        #pragma unroll
        for (int o = 8; o; o >>= 1) {
            pc += __shfl_xor_sync(0xFFFFFFFFu, pc, o);
            pd += __shfl_xor_sync(0xFFFFFFFFu, pd, o);
        }
        if ((tid & 15) == 0) { s_cn[row] = pc; s_qd[row] = pd; }

        float4 tv = make_float4(to_tf32(v.x), to_tf32(v.y), to_tf32(v.z), to_tf32(v.w));
        *(float4*)(bS + row * 64 + ((c4 ^ (row & 7)) << 2)) = tv;
    }
    if (tid < CC) s_mu[tid] = mus[tid];
    __syncthreads();

    if (wid == 0) {
        float qp = 0.f;
        #pragma unroll
        for (int j = lane; j < CC; j += 32)
            qp = fmaf(s_mu[j], rsq(fmaxf(s_qd[j], 1e-12f)), qp);
        #pragma unroll
        for (int o = 16; o; o >>= 1) qp += __shfl_xor_sync(0xFFFFFFFFu, qp, o);
        if (lane == 0) s_qpot = qp;
    }

    // -------- per-lane ldmatrix base addresses --------
    int mw = wid & 3, nw = wid >> 2;
    uint32_t aU = smem_u32(aS), bU = smem_u32(bS);
    uint32_t lr  = lane & 7, sel = lane >> 3;
    uint32_t csA = sel >> 1;                    // A: chunk parity select
    uint32_t baseA0 = aU + (mw * 32 + ((sel & 1) << 3) + lr) * 256;
    uint32_t baseA1 = baseA0 + 16 * 256;
    uint32_t csB = sel & 1;                     // B: chunk parity select
    uint32_t rB  = ((sel >> 1) << 3) + lr;

    int r = lane >> 2, qd = lane & 3;
    int m0 = mw * 32;

    // ==================== tile loop ====================
    for (int tile = blockIdx.x; tile < ntiles; tile += NWORK) {
        int base = tile * TILE_M;
        __syncthreads();   // previous tile fully consumed (aS, s_zn, s_pot free)

        // ---- stage A (candidates): coalesced LDG.128 -> STS.128 (raw fp32); row norms ----
        #pragma unroll
        for (int it = 0; it < 8; ++it) {
            int idx = tid + 256 * it;
            int row = idx >> 4, c4 = idx & 15;
            int ri = min(base + row, N - 1);
            float4 v = ((const float4*)cand)[(size_t)ri * 16 + c4];

            float pz = fmaf(v.x, v.x, fmaf(v.y, v.y, fmaf(v.z, v.z, v.w * v.w)));
            #pragma unroll
            for (int o = 8; o; o >>= 1) pz += __shfl_xor_sync(0xFFFFFFFFu, pz, o);
            if ((tid & 15) == 0) s_zn[row] = pz;

            *(float4*)(aS + row * 64 + ((c4 ^ (row & 7)) << 2)) = v;  // raw fp32; HMMA truncates
        }
        __syncthreads();

        // ---- two passes over N32 each: mainloop (32 accs) + partial epilogue ----
        float zn0 = s_zn[m0 + r],      zn1 = s_zn[m0 + 8 + r];
        float zn2 = s_zn[m0 + 16 + r], zn3 = s_zn[m0 + 24 + r];
        float p0 = 0.f, p1 = 0.f, p2 = 0.f, p3 = 0.f;

        #pragma unroll
        for (int pass = 0; pass < 2; ++pass) {
            uint32_t baseB0 = bU + (uint32_t)(nw * 64 + pass * 32 + rB) * 256;
            uint32_t baseB1 = baseB0 + 16 * 256;

            float acc[2][4][4];
            #pragma unroll
            for (int h = 0; h < 2; ++h)
                #pragma unroll
                for (int t = 0; t < 4; ++t) {
                    acc[h][t][0] = 0.f; acc[h][t][1] = 0.f;
                    acc[h][t][2] = 0.f; acc[h][t][3] = 0.f;
                }

            #pragma unroll
            for (uint32_t kb = 0; kb < 8; ++kb) {
                uint32_t offA = ((2 * kb + csA) ^ lr) << 4;
                uint32_t offB = ((2 * kb + csB) ^ lr) << 4;
                uint32_t a0, a1, a2, a3, c0, c1, c2, c3;
                ldsm_x4(a0, a1, a2, a3, baseA0 + offA);
                ldsm_x4(c0, c1, c2, c3, baseA1 + offA);
                uint32_t b0, b1, b2, b3;
                ldsm_x4(b0, b1, b2, b3, baseB0 + offB);
                mma_tf32(acc[0][0], a0, a1, a2, a3, b0, b1);
                mma_tf32(acc[0][1], a0, a1, a2, a3, b2, b3);
                mma_tf32(acc[1][0], c0, c1, c2, c3, b0, b1);
                mma_tf32(acc[1][1], c0, c1, c2, c3, b2, b3);
                ldsm_x4(b0, b1, b2, b3, baseB1 + offB);
                mma_tf32(acc[0][2], a0, a1, a2, a3, b0, b1);
                mma_tf32(acc[0][3], a0, a1, a2, a3, b2, b3);
                mma_tf32(acc[1][2], c0, c1, c2, c3, b0, b1);
                mma_tf32(acc[1][3], c0, c1, c2, c3, b2, b3);
            }

            // ---- partial epilogue: pot += mu * rsqrt(zn + cn - 2*dot) over this N32 ----
            #pragma unroll
            for (int t = 0; t < 4; ++t) {
                int j0 = nw * 64 + pass * 32 + t * 8 + qd * 2;
                float cn0 = s_cn[j0], cn1 = s_cn[j0 + 1];
                float mu0 = s_mu[j0], mu1 = s_mu[j0 + 1];
                float d;
                d = fmaf(acc[0][t][0], -2.f, zn0 + cn0); p0 = fmaf(mu0, rsq(d), p0);
                d = fmaf(acc[0][t][1], -2.f, zn0 + cn1); p0 = fmaf(mu1, rsq(d), p0);
                d = fmaf(acc[0][t][2], -2.f, zn1 + cn0); p1 = fmaf(mu0, rsq(d), p1);
                d = fmaf(acc[0][t][3], -2.f, zn1 + cn1); p1 = fmaf(mu1, rsq(d), p1);
                d = fmaf(acc[1][t][0], -2.f, zn2 + cn0); p2 = fmaf(mu0, rsq(d), p2);
                d = fmaf(acc[1][t][1], -2.f, zn2 + cn1); p2 = fmaf(mu1, rsq(d), p2);
                d = fmaf(acc[1][t][2], -2.f, zn3 + cn0); p3 = fmaf(mu0, rsq(d), p3);
                d = fmaf(acc[1][t][3], -2.f, zn3 + cn1); p3 = fmaf(mu1, rsq(d), p3);
            }
        }

        p0 += __shfl_xor_sync(0xFFFFFFFFu, p0, 1); p0 += __shfl_xor_sync(0xFFFFFFFFu, p0, 2);
        p1 += __shfl_xor_sync(0xFFFFFFFFu, p1, 1); p1 += __shfl_xor_sync(0xFFFFFFFFu, p1, 2);
        p2 += __shfl_xor_sync(0xFFFFFFFFu, p2, 1); p2 += __shfl_xor_sync(0xFFFFFFFFu, p2, 2);
        p3 += __shfl_xor_sync(0xFFFFFFFFu, p3, 1); p3 += __shfl_xor_sync(0xFFFFFFFFu, p3, 2);

        if (nw == 0 && qd == 0) {
            s_pot[m0 + r]      = p0;
            s_pot[m0 + 8 + r]  = p1;
            s_pot[m0 + 16 + r] = p2;
            s_pot[m0 + 24 + r] = p3;
        }
        __syncthreads();

        float es = 0.f;
        if (nw == 1 && qd == 0) {
            float qpot = s_qpot;
            float t0 = p0 + s_pot[m0 + r];
            float t1 = p1 + s_pot[m0 + 8 + r];
            float t2 = p2 + s_pot[m0 + 16 + r];
            float t3 = p3 + s_pot[m0 + 24 + r];
            int i0 = base + m0 + r;
            if (i0 < N)      { float e = __expf(-TINV * fabsf(qpot - t0)); att[i0]      = e; es += e; }
            if (i0 + 8 < N)  { float e = __expf(-TINV * fabsf(qpot - t1)); att[i0 + 8]  = e; es += e; }
            if (i0 + 16 < N) { float e = __expf(-TINV * fabsf(qpot - t2)); att[i0 + 16] = e; es += e; }
            if (i0 + 24 < N) { float e = __expf(-TINV * fabsf(qpot - t3)); att[i0 + 24] = e; es += e; }
        }
        #pragma unroll
        for (int o = 16; o; o >>= 1) es += __shfl_xor_sync(0xFFFFFFFFu, es, o);
        if (nw == 1 && lane == 0) s_red[mw] = es;
        __syncthreads();
        if (tid == 0)
            g_partial[tile] = s_red[0] + s_red[1] + s_red[2] + s_red[3];
    }
}

// ---------- reduce: total = sum of per-tile partials; g_inv = 1/total ----------
__global__ void reduce_kernel(int ntiles) {
    __shared__ float sh[16];
    int tid = threadIdx.x, lane = tid & 31;
    float s = 0.f;
    for (int i = tid; i < ntiles; i += 512) s += g_partial[i];
    #pragma unroll
    for (int o = 16; o; o >>= 1) s += __shfl_xor_sync(0xFFFFFFFFu, s, o);
    if (lane == 0) sh[tid >> 5] = s;
    __syncthreads();
    if (tid < 16) {
        float v = sh[tid];
        #pragma unroll
        for (int o = 8; o; o >>= 1) v += __shfl_xor_sync(0x0000FFFFu, v, o);
        if (tid == 0) g_inv = 1.0f / v;
    }
}

// ---------- normalize ----------
__global__ void norm_kernel(float* __restrict__ att, int N) {
    int i = blockIdx.x * blockDim.x + threadIdx.x;
    if (i < N) att[i] *= g_inv;
}

extern "C" void kernel_launch(void* const* d_in, const int* in_sizes, int n_in,
                              void* d_out, int out_size) {
    const float* q       = (const float*)d_in[0];
    const float* cand    = (const float*)d_in[1];
    const float* centers = (const float*)d_in[2];
    const float* mus     = (const float*)d_in[3];
    float* out = (float*)d_out;

    int N = in_sizes[1] / DD;   // 500000
    int ntiles = (N + TILE_M - 1) / TILE_M;

    cudaFuncSetAttribute(pot_kernel, cudaFuncAttributeMaxDynamicSharedMemorySize,
                         DSMEM_BYTES);

    pot_kernel<<<NWORK, 256, DSMEM_BYTES>>>(cand, centers, mus, q, out, out + DD, N, ntiles);
    reduce_kernel<<<1, 512>>>(ntiles);
    norm_kernel<<<(N + 255) / 256, 256>>>(out + DD, N);
}

// round 14
// speedup vs baseline: 1.7927x; 1.7927x over previous
#include <cuda_runtime.h>
#include <math.h>
#include <cstdint>

#define CC     128    // centers
#define DD     64     // latent dim
#define TILE_M 128    // candidates per tile
#define NWORK  296    // 2 CTAs x 148 SMs (proven optimum; 3/SM spills and regresses)
#define EPSF   1e-6f
#define TINV   10.0f  // 1/TEMP
#define DTF    0.1f

__device__ float g_partial[4096];
__device__ float g_inv;

// ---------------- helpers ----------------
__device__ __forceinline__ uint32_t smem_u32(const void* p) {
    uint32_t a;
    asm("{ .reg .u64 t; cvta.to.shared.u64 t, %1; cvt.u32.u64 %0, t; }" : "=r"(a) : "l"(p));
    return a;
}
__device__ __forceinline__ float to_tf32(float x) {
    uint32_t r;
    asm("cvt.rna.tf32.f32 %0, %1;" : "=r"(r) : "f"(x));
    return __uint_as_float(r);
}
__device__ __forceinline__ void ldsm_x4(uint32_t& r0, uint32_t& r1, uint32_t& r2, uint32_t& r3,
                                        uint32_t addr) {
    asm volatile("ldmatrix.sync.aligned.m8n8.x4.shared.b16 {%0,%1,%2,%3}, [%4];"
                 : "=r"(r0), "=r"(r1), "=r"(r2), "=r"(r3) : "r"(addr));
}
__device__ __forceinline__ void mma_tf32(float* c,
                                         uint32_t a0, uint32_t a1, uint32_t a2, uint32_t a3,
                                         uint32_t b0, uint32_t b1) {
    asm volatile("mma.sync.aligned.m16n8k8.row.col.f32.tf32.tf32.f32 "
                 "{%0,%1,%2,%3}, {%4,%5,%6,%7}, {%8,%9}, {%0,%1,%2,%3};"
                 : "+f"(c[0]), "+f"(c[1]), "+f"(c[2]), "+f"(c[3])
                 : "r"(a0), "r"(a1), "r"(a2), "r"(a3), "r"(b0), "r"(b1));
}
__device__ __forceinline__ float rsq(float x) {
    float r;
    asm("rsqrt.approx.f32 %0, %1;" : "=f"(r) : "f"(x));
    return r;
}

// dyn smem: A tile 32KB + B tile 32KB, row-major tf32 with 16B-chunk XOR swizzle
#define DSMEM_BYTES 65536

__global__ __launch_bounds__(256, 2)
void pot_kernel(const float* __restrict__ cand,
                const float* __restrict__ centers,
                const float* __restrict__ mus,
                const float* __restrict__ q,
                float* __restrict__ qout,
                float* __restrict__ att, int N, int ntiles) {
    extern __shared__ float dsm[];
    __shared__ float s_zn[TILE_M], s_cn[CC], s_mu[CC], s_qd[CC], s_pot[TILE_M], s_red[4];
    __shared__ float s_qpot;

    int tid  = threadIdx.x;
    int lane = tid & 31;
    int wid  = tid >> 5;

    float* aS = dsm;          // 8192 floats: 128 rows x 64, chunk(row,c4) at c4^(row&7)
    float* bS = dsm + 8192;   // same for centers

    // -------- query flow field (folded into last worker; dsm as scratch) --------
    if (blockIdx.x == NWORK - 1) {
        float* qs  = dsm;
        float* w   = dsm + 64;
        float* red = dsm + 192;
        if (tid < DD) qs[tid] = q[tid];
        __syncthreads();
        {
            int j = tid >> 1, h = tid & 1;
            const float4* cr = (const float4*)(centers + j * DD + h * 32);
            float d2 = 0.f;
            #pragma unroll
            for (int k2 = 0; k2 < 8; ++k2) {
                float4 v = cr[k2];
                float4 qv = *(const float4*)(qs + h * 32 + k2 * 4);
                float dx = v.x - qv.x, dy = v.y - qv.y, dz = v.z - qv.z, dw = v.w - qv.w;
                d2 = fmaf(dx, dx, fmaf(dy, dy, fmaf(dz, dz, fmaf(dw, dw, d2))));
            }
            d2 += __shfl_xor_sync(0xFFFFFFFFu, d2, 1);
            if (h == 0) {
                d2 = fmaxf(d2, 1e-12f);
                float r = sqrtf(d2);
                w[j] = mus[j] / (r * r * r + EPSF);
            }
        }
        __syncthreads();
        {
            int d = tid & 63, jg = tid >> 6;
            float s = 0.f;
            #pragma unroll 8
            for (int j2 = jg * 32; j2 < jg * 32 + 32; ++j2)
                s = fmaf(w[j2], centers[j2 * DD + d] - qs[d], s);
            red[tid] = s;
            __syncthreads();
            if (tid < DD)
                qout[tid] = fmaf(DTF, red[tid] + red[tid + 64] + red[tid + 128] + red[tid + 192],
                                 qs[tid]);
        }
        __syncthreads();   // scratch reuse barrier before B staging
    }

    // -------- stage B (centers) ONCE per CTA; norms + query dists --------
    #pragma unroll
    for (int it = 0; it < 8; ++it) {
        int idx = tid + 256 * it;              // 0..2047
        int row = idx >> 4, c4 = idx & 15;
        float4 v  = ((const float4*)centers)[row * 16 + c4];
        float4 qv = ((const float4*)q)[c4];

        float pc = fmaf(v.x, v.x, fmaf(v.y, v.y, fmaf(v.z, v.z, v.w * v.w)));
        float dx = v.x - qv.x, dy = v.y - qv.y, dz = v.z - qv.z, dw = v.w - qv.w;
        float pd = fmaf(dx, dx, fmaf(dy, dy, fmaf(dz, dz, dw * dw)));
        #pragma unroll
        for (int o = 8; o; o >>= 1) {
            pc += __shfl_xor_sync(0xFFFFFFFFu, pc, o);
            pd += __shfl_xor_sync(0xFFFFFFFFu, pd, o);
        }
        if ((tid & 15) == 0) { s_cn[row] = pc; s_qd[row] = pd; }

        float4 tv = make_float4(to_tf32(v.x), to_tf32(v.y), to_tf32(v.z), to_tf32(v.w));
        *(float4*)(bS + row * 64 + ((c4 ^ (row & 7)) << 2)) = tv;
    }
    if (tid < CC) s_mu[tid] = mus[tid];
    __syncthreads();

    if (wid == 0) {
        float qp = 0.f;
        #pragma unroll
        for (int j = lane; j < CC; j += 32)
            qp = fmaf(s_mu[j], rsq(fmaxf(s_qd[j], 1e-12f)), qp);
        #pragma unroll
        for (int o = 16; o; o >>= 1) qp += __shfl_xor_sync(0xFFFFFFFFu, qp, o);
        if (lane == 0) s_qpot = qp;
    }

    // -------- per-lane ldmatrix base addresses --------
    int mw = wid & 3, nw = wid >> 2;
    uint32_t aU = smem_u32(aS), bU = smem_u32(bS);
    uint32_t lr  = lane & 7, sel = lane >> 3;
    uint32_t csA = sel >> 1;                    // A: chunk parity select
    uint32_t baseA0 = aU + (mw * 32 + ((sel & 1) << 3) + lr) * 256;
    uint32_t baseA1 = baseA0 + 16 * 256;
    uint32_t csB = sel & 1;                     // B: chunk parity select
    uint32_t rB  = ((sel >> 1) << 3) + lr;
    uint32_t baseB0 = bU + (nw * 64 + 0  + rB) * 256;
    uint32_t baseB1 = bU + (nw * 64 + 16 + rB) * 256;
    uint32_t baseB2 = bU + (nw * 64 + 32 + rB) * 256;
    uint32_t baseB3 = bU + (nw * 64 + 48 + rB) * 256;

    int r = lane >> 2, qd = lane & 3;
    int m0 = mw * 32;

    // ==================== tile loop ====================
    for (int tile = blockIdx.x; tile < ntiles; tile += NWORK) {
        int base = tile * TILE_M;
        __syncthreads();   // previous tile fully consumed (aS, s_zn, s_pot free)

        // ---- stage A (candidates): coalesced LDG.128 -> STS.128; row norms ----
        #pragma unroll
        for (int it = 0; it < 8; ++it) {
            int idx = tid + 256 * it;
            int row = idx >> 4, c4 = idx & 15;
            int ri = min(base + row, N - 1);
            float4 v = ((const float4*)cand)[(size_t)ri * 16 + c4];

            float pz = fmaf(v.x, v.x, fmaf(v.y, v.y, fmaf(v.z, v.z, v.w * v.w)));
            #pragma unroll
            for (int o = 8; o; o >>= 1) pz += __shfl_xor_sync(0xFFFFFFFFu, pz, o);
            if ((tid & 15) == 0) s_zn[row] = pz;

            float4 tv = make_float4(to_tf32(v.x), to_tf32(v.y), to_tf32(v.z), to_tf32(v.w));
            *(float4*)(aS + row * 64 + ((c4 ^ (row & 7)) << 2)) = tv;
        }
        __syncthreads();

        // ---- mainloop: warp (mw,nw) = M32 x N64, K=64 via ldmatrix + mma.tf32 ----
        float acc[2][8][4];
        #pragma unroll
        for (int h = 0; h < 2; ++h)
            #pragma unroll
            for (int t = 0; t < 8; ++t) {
                acc[h][t][0] = 0.f; acc[h][t][1] = 0.f;
                acc[h][t][2] = 0.f; acc[h][t][3] = 0.f;
            }

        #pragma unroll
        for (uint32_t kb = 0; kb < 8; ++kb) {
            uint32_t offA = ((2 * kb + csA) ^ lr) << 4;
            uint32_t offB = ((2 * kb + csB) ^ lr) << 4;
            uint32_t a0, a1, a2, a3, c0, c1, c2, c3;
            ldsm_x4(a0, a1, a2, a3, baseA0 + offA);
            ldsm_x4(c0, c1, c2, c3, baseA1 + offA);
            uint32_t b0, b1, b2, b3;
            ldsm_x4(b0, b1, b2, b3, baseB0 + offB);
            mma_tf32(acc[0][0], a0, a1, a2, a3, b0, b1);
            mma_tf32(acc[0][1], a0, a1, a2, a3, b2, b3);
            mma_tf32(acc[1][0], c0, c1, c2, c3, b0, b1);
            mma_tf32(acc[1][1], c0, c1, c2, c3, b2, b3);
            ldsm_x4(b0, b1, b2, b3, baseB1 + offB);
            mma_tf32(acc[0][2], a0, a1, a2, a3, b0, b1);
            mma_tf32(acc[0][3], a0, a1, a2, a3, b2, b3);
            mma_tf32(acc[1][2], c0, c1, c2, c3, b0, b1);
            mma_tf32(acc[1][3], c0, c1, c2, c3, b2, b3);
            ldsm_x4(b0, b1, b2, b3, baseB2 + offB);
            mma_tf32(acc[0][4], a0, a1, a2, a3, b0, b1);
            mma_tf32(acc[0][5], a0, a1, a2, a3, b2, b3);
            mma_tf32(acc[1][4], c0, c1, c2, c3, b0, b1);
            mma_tf32(acc[1][5], c0, c1, c2, c3, b2, b3);
            ldsm_x4(b0, b1, b2, b3, baseB3 + offB);
            mma_tf32(acc[0][6], a0, a1, a2, a3, b0, b1);
            mma_tf32(acc[0][7], a0, a1, a2, a3, b2, b3);
            mma_tf32(acc[1][6], c0, c1, c2, c3, b0, b1);
            mma_tf32(acc[1][7], c0, c1, c2, c3, b2, b3);
        }

        // ---- epilogue: pot = sum_j mu_j * rsqrt(zn + cn_j - 2*dot) ----
        float zn0 = s_zn[m0 + r],      zn1 = s_zn[m0 + 8 + r];
        float zn2 = s_zn[m0 + 16 + r], zn3 = s_zn[m0 + 24 + r];
        float p0 = 0.f, p1 = 0.f, p2 = 0.f, p3 = 0.f;
        #pragma unroll
        for (int t = 0; t < 8; ++t) {
            int j0 = nw * 64 + t * 8 + qd * 2;
            float cn0 = s_cn[j0], cn1 = s_cn[j0 + 1];
            float mu0 = s_mu[j0], mu1 = s_mu[j0 + 1];
            float d;
            d = fmaf(acc[0][t][0], -2.f, zn0 + cn0); p0 = fmaf(mu0, rsq(d), p0);
            d = fmaf(acc[0][t][1], -2.f, zn0 + cn1); p0 = fmaf(mu1, rsq(d), p0);
            d = fmaf(acc[0][t][2], -2.f, zn1 + cn0); p1 = fmaf(mu0, rsq(d), p1);
            d = fmaf(acc[0][t][3], -2.f, zn1 + cn1); p1 = fmaf(mu1, rsq(d), p1);
            d = fmaf(acc[1][t][0], -2.f, zn2 + cn0); p2 = fmaf(mu0, rsq(d), p2);
            d = fmaf(acc[1][t][1], -2.f, zn2 + cn1); p2 = fmaf(mu1, rsq(d), p2);
            d = fmaf(acc[1][t][2], -2.f, zn3 + cn0); p3 = fmaf(mu0, rsq(d), p3);
            d = fmaf(acc[1][t][3], -2.f, zn3 + cn1); p3 = fmaf(mu1, rsq(d), p3);
        }
        p0 += __shfl_xor_sync(0xFFFFFFFFu, p0, 1); p0 += __shfl_xor_sync(0xFFFFFFFFu, p0, 2);
        p1 += __shfl_xor_sync(0xFFFFFFFFu, p1, 1); p1 += __shfl_xor_sync(0xFFFFFFFFu, p1, 2);
        p2 += __shfl_xor_sync(0xFFFFFFFFu, p2, 1); p2 += __shfl_xor_sync(0xFFFFFFFFu, p2, 2);
        p3 += __shfl_xor_sync(0xFFFFFFFFu, p3, 1); p3 += __shfl_xor_sync(0xFFFFFFFFu, p3, 2);

        if (nw == 0 && qd == 0) {
            s_pot[m0 + r]      = p0;
            s_pot[m0 + 8 + r]  = p1;
            s_pot[m0 + 16 + r] = p2;
            s_pot[m0 + 24 + r] = p3;
        }
        __syncthreads();

        float es = 0.f;
        if (nw == 1 && qd == 0) {
            float qpot = s_qpot;
            float t0 = p0 + s_pot[m0 + r];
            float t1 = p1 + s_pot[m0 + 8 + r];
            float t2 = p2 + s_pot[m0 + 16 + r];
            float t3 = p3 + s_pot[m0 + 24 + r];
            int i0 = base + m0 + r;
            if (i0 < N)      { float e = __expf(-TINV * fabsf(qpot - t0)); att[i0]      = e; es += e; }
            if (i0 + 8 < N)  { float e = __expf(-TINV * fabsf(qpot - t1)); att[i0 + 8]  = e; es += e; }
            if (i0 + 16 < N) { float e = __expf(-TINV * fabsf(qpot - t2)); att[i0 + 16] = e; es += e; }
            if (i0 + 24 < N) { float e = __expf(-TINV * fabsf(qpot - t3)); att[i0 + 24] = e; es += e; }
        }
        #pragma unroll
        for (int o = 16; o; o >>= 1) es += __shfl_xor_sync(0xFFFFFFFFu, es, o);
        if (nw == 1 && lane == 0) s_red[mw] = es;
        __syncthreads();
        if (tid == 0)
            g_partial[tile] = s_red[0] + s_red[1] + s_red[2] + s_red[3];
    }
}

// ---------- reduce: total = sum of per-tile partials; g_inv = 1/total ----------
__global__ void reduce_kernel(int ntiles) {
    __shared__ float sh[32];
    int tid = threadIdx.x, lane = tid & 31;
    float s = 0.f;
    for (int i = tid; i < ntiles; i += 1024) s += g_partial[i];
    #pragma unroll
    for (int o = 16; o; o >>= 1) s += __shfl_xor_sync(0xFFFFFFFFu, s, o);
    if (lane == 0) sh[tid >> 5] = s;
    __syncthreads();
    if (tid < 32) {
        float v = sh[tid];
        #pragma unroll
        for (int o = 16; o; o >>= 1) v += __shfl_xor_sync(0xFFFFFFFFu, v, o);
        if (tid == 0) g_inv = 1.0f / v;
    }
}

// ---------- normalize (float4: N divisible by 4, att 256B-aligned) ----------
__global__ void norm_kernel(float4* __restrict__ att4, int n4) {
    int i = blockIdx.x * blockDim.x + threadIdx.x;
    if (i < n4) {
        float inv = g_inv;
        float4 v = att4[i];
        v.x *= inv; v.y *= inv; v.z *= inv; v.w *= inv;
        att4[i] = v;
    }
}

extern "C" void kernel_launch(void* const* d_in, const int* in_sizes, int n_in,
                              void* d_out, int out_size) {
    const float* q       = (const float*)d_in[0];
    const float* cand    = (const float*)d_in[1];
    const float* centers = (const float*)d_in[2];
    const float* mus     = (const float*)d_in[3];
    float* out = (float*)d_out;

    int N = in_sizes[1] / DD;   // 500000
    int ntiles = (N + TILE_M - 1) / TILE_M;

    cudaFuncSetAttribute(pot_kernel, cudaFuncAttributeMaxDynamicSharedMemorySize,
                         DSMEM_BYTES);

    pot_kernel<<<NWORK, 256, DSMEM_BYTES>>>(cand, centers, mus, q, out, out + DD, N, ntiles);
    reduce_kernel<<<1, 1024>>>(ntiles);
    int n4 = N / 4;   // N = 500000, divisible by 4
    norm_kernel<<<(n4 + 255) / 256, 256>>>((float4*)(out + DD), n4);
}